// round 4
// baseline (speedup 1.0000x reference)
#include <cuda_runtime.h>
#include <math.h>

#define NN 100000
#define EE 600000

// ---------------- scratch (static device globals; no allocation) ----------------
__device__ float g_q[NN * 128];
__device__ float g_k[NN * 128];
__device__ float g_v[NN * 128];
__device__ float g_skip[NN * 128];
__device__ float g_denom[NN * 2];

// ---------------- kernel 0: zero accumulators ----------------
__global__ void init_zero_kernel(float* __restrict__ out) {
    int i = blockIdx.x * blockDim.x + threadIdx.x;
    if (i < NN * 128) out[i] = 0.0f;
    if (i < NN * 2) g_denom[i] = 0.0f;
}

// ---------------- kernel 1: node projections q,k,v,skip ----------------
// 512 threads: thread -> (matrix m = tid>>7, col = tid&127). 64 nodes per block.
__global__ __launch_bounds__(512) void proj_kernel(
    const float* __restrict__ x,
    const float* __restrict__ Wq, const float* __restrict__ bq,
    const float* __restrict__ Wk, const float* __restrict__ bk,
    const float* __restrict__ Wv, const float* __restrict__ bv,
    const float* __restrict__ Ws, const float* __restrict__ bs)
{
    __shared__ float xs[64][128];
    const int node0 = blockIdx.x * 64;
    const int tid = threadIdx.x;

    // stage 64 x-rows (guard past N with zeros)
    for (int i = tid; i < 64 * 32; i += 512) {
        int r = i >> 5;            // row 0..63
        int c4 = i & 31;           // float4 index 0..31
        int node = node0 + r;
        float4 val = make_float4(0.f, 0.f, 0.f, 0.f);
        if (node < NN) val = reinterpret_cast<const float4*>(x + (size_t)node * 128)[c4];
        reinterpret_cast<float4*>(&xs[r][0])[c4] = val;
    }
    __syncthreads();

    const int m = tid >> 7;
    const int col = tid & 127;
    const float* W;
    const float* b;
    float* outp;
    if (m == 0)      { W = Wq; b = bq; outp = g_q; }
    else if (m == 1) { W = Wk; b = bk; outp = g_k; }
    else if (m == 2) { W = Wv; b = bv; outp = g_v; }
    else             { W = Ws; b = bs; outp = g_skip; }
    const float bias = b[col];

    for (int n0 = 0; n0 < 64; n0 += 16) {
        float acc[16];
#pragma unroll
        for (int r = 0; r < 16; r++) acc[r] = 0.0f;
#pragma unroll 4
        for (int k = 0; k < 128; k++) {
            float w = W[k * 128 + col];
#pragma unroll
            for (int r = 0; r < 16; r++) acc[r] = fmaf(xs[n0 + r][k], w, acc[r]);
        }
#pragma unroll
        for (int r = 0; r < 16; r++) {
            int node = node0 + n0 + r;
            if (node < NN) outp[(size_t)node * 128 + col] = acc[r] + bias;
        }
    }
}

// ---------------- kernel 2: fused edge pass ----------------
// 256 threads = 8 warps. We (64KB) in smem; each warp owns attr scratch for 8 edges.
// Per 8-edge group: build edge_attr (cos time-enc | msg), GEMV against We,
// gather q[dst], k[src], v[src], per-head dot -> exp, atomic scatter of
// exp * (v + e) into out and exp into denom.
__global__ __launch_bounds__(256) void edge_kernel(
    const int* __restrict__ ei,          // [2, E]
    const float* __restrict__ tarr,      // [E]
    const float* __restrict__ lastu,     // [N]
    const float* __restrict__ msg,       // [E, 64]
    const float* __restrict__ wt,        // [64]
    const float* __restrict__ bt,        // [64]
    const float* __restrict__ We,        // [128, 128]
    float* __restrict__ out)             // [N, 128] accumulator
{
    extern __shared__ float sm[];
    float* We_s = sm;                    // 16384 floats
    float* attr_s = sm + 16384;          // 8 warps * 8 edges * 128

    const int tid = threadIdx.x;
    // stage We
    for (int i = tid; i < 4096; i += 256)
        reinterpret_cast<float4*>(We_s)[i] = reinterpret_cast<const float4*>(We)[i];
    __syncthreads();

    const int warp = tid >> 5;
    const int lane = tid & 31;
    float* attr_w = attr_s + warp * 1024;

    const float wt0 = wt[lane], wt1 = wt[lane + 32];
    const float bt0 = bt[lane], bt1 = bt[lane + 32];

    const long gw = (long)blockIdx.x * 8 + warp;
    const long nwarps = (long)gridDim.x * 8;

    for (long base = gw * 8; base < EE; base += nwarps * 8) {
        int myE = (int)((EE - base) < 8 ? (EE - base) : 8);

        int s_r = 0, d_r = 0;
        float rel_r = 0.0f;
        if (lane < myE) {
            long e = base + lane;
            s_r = ei[e];
            d_r = ei[EE + e];
            rel_r = lastu[s_r] - tarr[e];
        }

        // build edge_attr for the group
        for (int mm = 0; mm < 8; mm++) {
            if (mm >= myE) break;
            float rel = __shfl_sync(0xffffffffu, rel_r, mm);
            long e = base + mm;
            attr_w[mm * 128 + lane]      = cosf(fmaf(rel, wt0, bt0));
            attr_w[mm * 128 + lane + 32] = cosf(fmaf(rel, wt1, bt1));
            attr_w[mm * 128 + lane + 64] = msg[e * 64 + lane];
            attr_w[mm * 128 + lane + 96] = msg[e * 64 + lane + 32];
        }
        __syncwarp();

        // e = attr @ We ; lane owns cols [lane*4, lane*4+3]
        float acc[8][4];
#pragma unroll
        for (int mm = 0; mm < 8; mm++)
#pragma unroll
            for (int c = 0; c < 4; c++) acc[mm][c] = 0.0f;

        const float4* We4 = reinterpret_cast<const float4*>(We_s);
#pragma unroll 4
        for (int k = 0; k < 128; k++) {
            float4 w = We4[k * 32 + lane];
#pragma unroll
            for (int mm = 0; mm < 8; mm++) {
                float a = attr_w[mm * 128 + k];
                acc[mm][0] = fmaf(a, w.x, acc[mm][0]);
                acc[mm][1] = fmaf(a, w.y, acc[mm][1]);
                acc[mm][2] = fmaf(a, w.z, acc[mm][2]);
                acc[mm][3] = fmaf(a, w.w, acc[mm][3]);
            }
        }

        // attention + scatter per edge
        for (int mm = 0; mm < 8; mm++) {
            if (mm >= myE) break;
            int s = __shfl_sync(0xffffffffu, s_r, mm);
            int d = __shfl_sync(0xffffffffu, d_r, mm);

            float4 q4 = reinterpret_cast<const float4*>(g_q + (size_t)d * 128)[lane];
            float4 k4 = reinterpret_cast<const float4*>(g_k + (size_t)s * 128)[lane];
            float4 v4 = reinterpret_cast<const float4*>(g_v + (size_t)s * 128)[lane];

            float kj0 = k4.x + acc[mm][0];
            float kj1 = k4.y + acc[mm][1];
            float kj2 = k4.z + acc[mm][2];
            float kj3 = k4.w + acc[mm][3];

            float p = q4.x * kj0 + q4.y * kj1 + q4.z * kj2 + q4.w * kj3;
            // reduce within each 16-lane half (head 0: lanes 0-15, head 1: 16-31)
            p += __shfl_xor_sync(0xffffffffu, p, 1);
            p += __shfl_xor_sync(0xffffffffu, p, 2);
            p += __shfl_xor_sync(0xffffffffu, p, 4);
            p += __shfl_xor_sync(0xffffffffu, p, 8);

            float ex = expf(p * 0.125f);   // 1/sqrt(64)

            float o0 = ex * (v4.x + acc[mm][0]);
            float o1 = ex * (v4.y + acc[mm][1]);
            float o2 = ex * (v4.z + acc[mm][2]);
            float o3 = ex * (v4.w + acc[mm][3]);

            float* op = out + (size_t)d * 128 + lane * 4;
            atomicAdd(op + 0, o0);
            atomicAdd(op + 1, o1);
            atomicAdd(op + 2, o2);
            atomicAdd(op + 3, o3);

            if (lane == 0)  atomicAdd(&g_denom[(size_t)d * 2 + 0], ex);
            if (lane == 16) atomicAdd(&g_denom[(size_t)d * 2 + 1], ex);
        }
        __syncwarp();
    }
}

// ---------------- kernel 3: finalize out = acc/denom + skip ----------------
__global__ void finalize_kernel(float* __restrict__ out) {
    int i = blockIdx.x * blockDim.x + threadIdx.x;
    if (i >= NN * 128) return;
    int n = i >> 7;
    int c = i & 127;
    int h = c >> 6;
    float den = g_denom[n * 2 + h] + 1e-16f;
    out[i] = out[i] / den + g_skip[i];
}

// ---------------- launcher ----------------
extern "C" void kernel_launch(void* const* d_in, const int* in_sizes, int n_in,
                              void* d_out, int out_size)
{
    const float* x     = (const float*)d_in[0];
    const float* lastu = (const float*)d_in[1];
    const int*   ei    = (const int*)d_in[2];
    const float* tarr  = (const float*)d_in[3];
    const float* msg   = (const float*)d_in[4];
    const float* wt    = (const float*)d_in[5];
    const float* bt    = (const float*)d_in[6];
    const float* Wq    = (const float*)d_in[7];
    const float* bq    = (const float*)d_in[8];
    const float* Wk    = (const float*)d_in[9];
    const float* bk    = (const float*)d_in[10];
    const float* Wv    = (const float*)d_in[11];
    const float* bv    = (const float*)d_in[12];
    const float* We    = (const float*)d_in[13];
    const float* Ws    = (const float*)d_in[14];
    const float* bs    = (const float*)d_in[15];
    float* out = (float*)d_out;

    init_zero_kernel<<<(NN * 128 + 511) / 512, 512>>>(out);

    proj_kernel<<<(NN + 63) / 64, 512>>>(x, Wq, bq, Wk, bk, Wv, bv, Ws, bs);

    const int smem = (16384 + 8 * 1024) * sizeof(float);   // 98304 bytes
    cudaFuncSetAttribute(edge_kernel, cudaFuncAttributeMaxDynamicSharedMemorySize, smem);
    edge_kernel<<<1184, 256, smem>>>(ei, tarr, lastu, msg, wt, bt, We, out);

    finalize_kernel<<<(NN * 128 + 255) / 256, 256>>>(out);
}

// round 5
// speedup vs baseline: 1.0648x; 1.0648x over previous
#include <cuda_runtime.h>
#include <math.h>

#define NN 100000
#define EE 600000

// ---------------- scratch (static device globals; no allocation) ----------------
__device__ __align__(16) float g_q[NN * 128];
__device__ __align__(16) float g_k[NN * 128];
__device__ __align__(16) float g_v[NN * 128];
__device__ __align__(16) float g_skip[NN * 128];
__device__ __align__(16) float g_denom[NN * 2];

// ---------------- f32x2 packed helpers ----------------
__device__ __forceinline__ unsigned long long pk2(float lo, float hi) {
    unsigned long long r;
    asm("mov.b64 %0, {%1, %2};" : "=l"(r) : "f"(lo), "f"(hi));
    return r;
}
__device__ __forceinline__ float2 upk2(unsigned long long v) {
    float2 r;
    asm("mov.b64 {%0, %1}, %2;" : "=f"(r.x), "=f"(r.y) : "l"(v));
    return r;
}
__device__ __forceinline__ void ffma2(unsigned long long& d, unsigned long long a, unsigned long long b) {
    asm("fma.rn.f32x2 %0, %1, %2, %0;" : "+l"(d) : "l"(a), "l"(b));
}

// ---------------- kernel 0: zero accumulators ----------------
__global__ void init_zero_kernel(float4* __restrict__ out4) {
    int i = blockIdx.x * blockDim.x + threadIdx.x;
    if (i < NN * 32) out4[i] = make_float4(0.f, 0.f, 0.f, 0.f);
    if (i < NN * 2) g_denom[i] = 0.0f;
}

// ---------------- kernel 1: node projections q,k,v,skip (f32x2) ----------------
// 512 threads: m = tid>>7 selects matrix, col = tid&127. 64 nodes per block.
// x tile staged TRANSPOSED: xs[k][r] so row-pairs pack into f32x2 operands.
__global__ __launch_bounds__(512) void proj_kernel(
    const float* __restrict__ x,
    const float* __restrict__ Wq, const float* __restrict__ bq,
    const float* __restrict__ Wk, const float* __restrict__ bk,
    const float* __restrict__ Wv, const float* __restrict__ bv,
    const float* __restrict__ Ws, const float* __restrict__ bs)
{
    __shared__ __align__(16) float xs[128][64];   // [k][r]
    const int node0 = blockIdx.x * 64;
    const int tid = threadIdx.x;

    // stage transposed. Warp-mapping: c4 = tid>>6 fixed per warp, r = tid&63
    // -> lanes differ in r => conflict-free STS; LDG is 16B-per-row gather
    // (stays hot in L1/L2 since the whole block touches the same 32KB tile).
    for (int i = tid; i < 2048; i += 512) {
        int c4 = i >> 6;           // float4 chunk 0..31
        int r  = i & 63;           // row 0..63
        int node = node0 + r;
        float4 v = make_float4(0.f, 0.f, 0.f, 0.f);
        if (node < NN) v = reinterpret_cast<const float4*>(x + (size_t)node * 128)[c4];
        xs[c4 * 4 + 0][r] = v.x;
        xs[c4 * 4 + 1][r] = v.y;
        xs[c4 * 4 + 2][r] = v.z;
        xs[c4 * 4 + 3][r] = v.w;
    }
    __syncthreads();

    const int m = tid >> 7;
    const int col = tid & 127;
    const float* W; const float* b; float* outp;
    if (m == 0)      { W = Wq; b = bq; outp = g_q; }
    else if (m == 1) { W = Wk; b = bk; outp = g_k; }
    else if (m == 2) { W = Wv; b = bv; outp = g_v; }
    else             { W = Ws; b = bs; outp = g_skip; }
    const float bias = b[col];

    unsigned long long acc[32];   // acc[j] = rows (2j, 2j+1) for this col
#pragma unroll
    for (int j = 0; j < 32; j++) acc[j] = 0ull;

#pragma unroll 4
    for (int k = 0; k < 128; k++) {
        float w = W[k * 128 + col];
        unsigned long long w2 = pk2(w, w);
        const ulonglong2* xr = reinterpret_cast<const ulonglong2*>(&xs[k][0]); // 16 x (2 pairs)
#pragma unroll
        for (int j = 0; j < 16; j++) {
            ulonglong2 a = xr[j];          // LDS.128 broadcast: 4 rows
            ffma2(acc[2 * j],     a.x, w2);
            ffma2(acc[2 * j + 1], a.y, w2);
        }
    }

#pragma unroll
    for (int j = 0; j < 32; j++) {
        float2 v = upk2(acc[j]);
        int r0 = 2 * j;
        int n0 = node0 + r0;
        if (n0 < NN)     outp[(size_t)n0 * 128 + col]       = v.x + bias;
        if (n0 + 1 < NN) outp[(size_t)(n0 + 1) * 128 + col] = v.y + bias;
    }
}

// ---------------- kernel 2: fused edge pass (f32x2 GEMV) ----------------
// 512 threads = 16 warps, persistent grid of 148 blocks. We (64KB) in smem.
// attr stored TRANSPOSED per warp: attr_t[k][mm], stride 10 floats per k
// (8B-aligned rows for LDS.64 pairs, <=2-way STS conflicts).
#define ATTR_STRIDE 10

__global__ __launch_bounds__(512) void edge_kernel(
    const int* __restrict__ ei,
    const float* __restrict__ tarr,
    const float* __restrict__ lastu,
    const float* __restrict__ msg,
    const float* __restrict__ wt,
    const float* __restrict__ bt,
    const float* __restrict__ We,
    float* __restrict__ out)
{
    extern __shared__ __align__(16) float sm[];
    float* We_s = sm;                            // 16384 floats
    float* attr_s = sm + 16384;                  // 16 warps * 128*ATTR_STRIDE

    const int tid = threadIdx.x;
    for (int i = tid; i < 4096; i += 512)
        reinterpret_cast<float4*>(We_s)[i] = reinterpret_cast<const float4*>(We)[i];
    __syncthreads();

    const int warp = tid >> 5;
    const int lane = tid & 31;
    float* attr_w = attr_s + warp * (128 * ATTR_STRIDE);

    const float wt0 = wt[lane], wt1 = wt[lane + 32];
    const float bt0 = bt[lane], bt1 = bt[lane + 32];

    const long gw = (long)blockIdx.x * 16 + warp;
    const long nwarps = (long)gridDim.x * 16;

    for (long base = gw * 8; base < EE; base += nwarps * 8) {
        int myE = (int)((EE - base) < 8 ? (EE - base) : 8);

        int s_r = 0, d_r = 0;
        float rel_r = 0.0f;
        if (lane < myE) {
            long e = base + lane;
            s_r = ei[e];
            d_r = ei[EE + e];
            rel_r = lastu[s_r] - tarr[e];
        }

        // build transposed edge_attr: attr_w[k*ATTR_STRIDE + mm]
        for (int mm = 0; mm < 8; mm++) {
            if (mm >= myE) break;
            float rel = __shfl_sync(0xffffffffu, rel_r, mm);
            long e = base + mm;
            attr_w[lane * ATTR_STRIDE + mm]        = cosf(fmaf(rel, wt0, bt0));
            attr_w[(lane + 32) * ATTR_STRIDE + mm] = cosf(fmaf(rel, wt1, bt1));
            attr_w[(lane + 64) * ATTR_STRIDE + mm] = msg[e * 64 + lane];
            attr_w[(lane + 96) * ATTR_STRIDE + mm] = msg[e * 64 + lane + 32];
        }
        __syncwarp();

        // e = attr @ We ; lane owns cols [lane*4 .. lane*4+3]
        // acc[p][c]: edge-pair (2p, 2p+1), column c  -- packed f32x2 over edges
        unsigned long long acc[4][4];
#pragma unroll
        for (int p = 0; p < 4; p++)
#pragma unroll
            for (int c = 0; c < 4; c++) acc[p][c] = 0ull;

        const float4* We4 = reinterpret_cast<const float4*>(We_s);
#pragma unroll 4
        for (int k = 0; k < 128; k++) {
            float4 w = We4[k * 32 + lane];
            unsigned long long wx = pk2(w.x, w.x);
            unsigned long long wy = pk2(w.y, w.y);
            unsigned long long wz = pk2(w.z, w.z);
            unsigned long long ww = pk2(w.w, w.w);
            const unsigned long long* ap =
                reinterpret_cast<const unsigned long long*>(attr_w + k * ATTR_STRIDE);
            unsigned long long a0 = ap[0], a1 = ap[1], a2 = ap[2], a3 = ap[3];
            ffma2(acc[0][0], a0, wx); ffma2(acc[0][1], a0, wy);
            ffma2(acc[0][2], a0, wz); ffma2(acc[0][3], a0, ww);
            ffma2(acc[1][0], a1, wx); ffma2(acc[1][1], a1, wy);
            ffma2(acc[1][2], a1, wz); ffma2(acc[1][3], a1, ww);
            ffma2(acc[2][0], a2, wx); ffma2(acc[2][1], a2, wy);
            ffma2(acc[2][2], a2, wz); ffma2(acc[2][3], a2, ww);
            ffma2(acc[3][0], a3, wx); ffma2(acc[3][1], a3, wy);
            ffma2(acc[3][2], a3, wz); ffma2(acc[3][3], a3, ww);
        }

        // attention + scatter per edge
        for (int mm = 0; mm < 8; mm++) {
            if (mm >= myE) break;
            int s = __shfl_sync(0xffffffffu, s_r, mm);
            int d = __shfl_sync(0xffffffffu, d_r, mm);

            float em[4];
#pragma unroll
            for (int c = 0; c < 4; c++) {
                float2 t = upk2(acc[mm >> 1][c]);
                em[c] = (mm & 1) ? t.y : t.x;
            }

            float4 q4 = reinterpret_cast<const float4*>(g_q + (size_t)d * 128)[lane];
            float4 k4 = reinterpret_cast<const float4*>(g_k + (size_t)s * 128)[lane];
            float4 v4 = reinterpret_cast<const float4*>(g_v + (size_t)s * 128)[lane];

            float kj0 = k4.x + em[0];
            float kj1 = k4.y + em[1];
            float kj2 = k4.z + em[2];
            float kj3 = k4.w + em[3];

            float p = q4.x * kj0 + q4.y * kj1 + q4.z * kj2 + q4.w * kj3;
            p += __shfl_xor_sync(0xffffffffu, p, 1);
            p += __shfl_xor_sync(0xffffffffu, p, 2);
            p += __shfl_xor_sync(0xffffffffu, p, 4);
            p += __shfl_xor_sync(0xffffffffu, p, 8);

            float ex = expf(p * 0.125f);   // 1/sqrt(64)

            float o0 = ex * (v4.x + em[0]);
            float o1 = ex * (v4.y + em[1]);
            float o2 = ex * (v4.z + em[2]);
            float o3 = ex * (v4.w + em[3]);

            float* op = out + (size_t)d * 128 + lane * 4;
            atomicAdd(op + 0, o0);
            atomicAdd(op + 1, o1);
            atomicAdd(op + 2, o2);
            atomicAdd(op + 3, o3);

            if (lane == 0)  atomicAdd(&g_denom[(size_t)d * 2 + 0], ex);
            if (lane == 16) atomicAdd(&g_denom[(size_t)d * 2 + 1], ex);
        }
        __syncwarp();
    }
}

// ---------------- kernel 3: finalize out = acc/denom + skip (float4) ----------------
__global__ void finalize_kernel(float4* __restrict__ out4) {
    int i = blockIdx.x * blockDim.x + threadIdx.x;   // float4 index
    if (i >= NN * 32) return;
    int n = i >> 5;
    int c4 = i & 31;
    int h = c4 >> 4;
    float inv = 1.0f / (g_denom[n * 2 + h] + 1e-16f);
    float4 o = out4[i];
    float4 s = reinterpret_cast<const float4*>(g_skip)[i];
    o.x = o.x * inv + s.x;
    o.y = o.y * inv + s.y;
    o.z = o.z * inv + s.z;
    o.w = o.w * inv + s.w;
    out4[i] = o;
}

// ---------------- launcher ----------------
extern "C" void kernel_launch(void* const* d_in, const int* in_sizes, int n_in,
                              void* d_out, int out_size)
{
    const float* x     = (const float*)d_in[0];
    const float* lastu = (const float*)d_in[1];
    const int*   ei    = (const int*)d_in[2];
    const float* tarr  = (const float*)d_in[3];
    const float* msg   = (const float*)d_in[4];
    const float* wt    = (const float*)d_in[5];
    const float* bt    = (const float*)d_in[6];
    const float* Wq    = (const float*)d_in[7];
    const float* bq    = (const float*)d_in[8];
    const float* Wk    = (const float*)d_in[9];
    const float* bk    = (const float*)d_in[10];
    const float* Wv    = (const float*)d_in[11];
    const float* bv    = (const float*)d_in[12];
    const float* We    = (const float*)d_in[13];
    const float* Ws    = (const float*)d_in[14];
    const float* bs    = (const float*)d_in[15];
    float* out = (float*)d_out;

    init_zero_kernel<<<(NN * 32 + 511) / 512, 512>>>((float4*)out);

    proj_kernel<<<(NN + 63) / 64, 512>>>(x, Wq, bq, Wk, bk, Wv, bv, Ws, bs);

    const int smem = (16384 + 16 * 128 * ATTR_STRIDE) * sizeof(float);  // 147456 B
    cudaFuncSetAttribute(edge_kernel, cudaFuncAttributeMaxDynamicSharedMemorySize, smem);
    edge_kernel<<<148, 512, smem>>>(ei, tarr, lastu, msg, wt, bt, We, out);

    finalize_kernel<<<(NN * 32 + 255) / 256, 256>>>((float4*)out);
}